// round 1
// baseline (speedup 1.0000x reference)
#include <cuda_runtime.h>
#include <cstdint>

#define NB_SEQ   2000
#define NB_EVENT 2000
#define NB_TYPE  10
#define PRED_LEN 1000

// Single-block kernel. Phases:
//  A) copy train block (20000 floats) to out[0 : 20000]
//  B) S0[k] = sum_e seq[e][k] * exp(-w[k]*(2000-e))        (warp per k)
//  C) term1[i][k] = spont/theta*(exp(-th*t) - exp(-th*(t+1))), t = 2000+i
//     precomputed for all 1000 steps into shared memory (off the critical path)
//  D) warp 0 runs the 1000-step scan; lane k owns type k.
__global__ __launch_bounds__(1024, 1)
void hawkes_kernel(const int* __restrict__ seq_id,
                   const float* __restrict__ sequences,
                   const float* __restrict__ spontaneous,
                   const float* __restrict__ theta,
                   const float* __restrict__ w,
                   const float* __restrict__ alpha,
                   float* __restrict__ out)
{
    __shared__ float s_term1[PRED_LEN * NB_TYPE];   // 40 KB
    __shared__ float s_S0[NB_TYPE];

    const int tid  = threadIdx.x;
    const int wid  = tid >> 5;
    const int lane = tid & 31;

    const int sid = seq_id[0];
    const float* __restrict__ seq = sequences + (size_t)sid * NB_EVENT * NB_TYPE;

    // ---- Phase A: copy training block (coalesced) ----
    #pragma unroll 4
    for (int i = tid; i < NB_EVENT * NB_TYPE; i += 1024) {
        out[i] = seq[i];
    }

    // ---- Phase B: S0 per type, one warp per k ----
    if (wid < NB_TYPE) {
        const int k = wid;
        const float wk = w[sid * NB_TYPE + k];
        float acc = 0.0f;
        for (int e = lane; e < NB_EVENT; e += 32) {
            float d = expf(-wk * (float)(NB_EVENT - e));
            acc += seq[e * NB_TYPE + k] * d;
        }
        #pragma unroll
        for (int off = 16; off > 0; off >>= 1)
            acc += __shfl_xor_sync(0xFFFFFFFFu, acc, off);
        if (lane == 0) s_S0[k] = acc;
    }

    // ---- Phase C: precompute term1 for all predicted steps ----
    for (int idx = tid; idx < PRED_LEN * NB_TYPE; idx += 1024) {
        const int i = idx / NB_TYPE;
        const int k = idx - i * NB_TYPE;
        const float th = theta[sid * NB_TYPE + k];
        const float sp = spontaneous[sid * NB_TYPE + k];
        const float t  = (float)(NB_EVENT + i);
        const float e0 = expf(-th * t);
        const float e1 = expf(-th * (t + 1.0f));
        s_term1[idx] = sp / th * (e0 - e1);
    }

    __syncthreads();

    // ---- Phase D: sequential scan, warp 0, lane k = type k ----
    if (wid != 0) return;

    const bool act = (lane < NB_TYPE);
    const int  k   = act ? lane : 0;

    float S        = act ? s_S0[k] : 0.0f;
    const float wk = act ? w[sid * NB_TYPE + k] : 1.0f;
    const float ew = act ? expf(-wk) : 0.0f;
    const float om = 1.0f - ew;      // (1 - exp(-w))
    const float rw = 1.0f / wk;

    float a0,a1,a2,a3,a4,a5,a6,a7,a8,a9;
    {
        const float* ar = alpha + ((size_t)sid * NB_TYPE + k) * NB_TYPE;
        a0 = act ? ar[0] : 0.0f;  a1 = act ? ar[1] : 0.0f;
        a2 = act ? ar[2] : 0.0f;  a3 = act ? ar[3] : 0.0f;
        a4 = act ? ar[4] : 0.0f;  a5 = act ? ar[5] : 0.0f;
        a6 = act ? ar[6] : 0.0f;  a7 = act ? ar[7] : 0.0f;
        a8 = act ? ar[8] : 0.0f;  a9 = act ? ar[9] : 0.0f;
    }

    float* __restrict__ outp = out + NB_EVENT * NB_TYPE;

    #pragma unroll 4
    for (int i = 0; i < PRED_LEN; i++) {
        const float eff = S * om;

        const float e0 = __shfl_sync(0xFFFFFFFFu, eff, 0);
        const float e1 = __shfl_sync(0xFFFFFFFFu, eff, 1);
        const float e2 = __shfl_sync(0xFFFFFFFFu, eff, 2);
        const float e3 = __shfl_sync(0xFFFFFFFFu, eff, 3);
        const float e4 = __shfl_sync(0xFFFFFFFFu, eff, 4);
        const float e5 = __shfl_sync(0xFFFFFFFFu, eff, 5);
        const float e6 = __shfl_sync(0xFFFFFFFFu, eff, 6);
        const float e7 = __shfl_sync(0xFFFFFFFFu, eff, 7);
        const float e8 = __shfl_sync(0xFFFFFFFFu, eff, 8);
        const float e9 = __shfl_sync(0xFFFFFFFFu, eff, 9);

        // 10 independent products, then a shallow add tree (depth ~4)
        const float p0 = a0 * e0, p1 = a1 * e1, p2 = a2 * e2, p3 = a3 * e3;
        const float p4 = a4 * e4, p5 = a5 * e5, p6 = a6 * e6, p7 = a7 * e7;
        const float p8 = a8 * e8, p9 = a9 * e9;
        const float q0 = p0 + p1, q1 = p2 + p3, q2 = p4 + p5, q3 = p6 + p7, q4 = p8 + p9;
        const float r0 = q0 + q1, r1 = q2 + q3;
        const float t2 = (r0 + r1) + q4;

        const float pred = s_term1[i * NB_TYPE + k] + t2 * rw;
        if (act) outp[i * NB_TYPE + k] = pred;
        S = ew * (S + pred);
    }
}

extern "C" void kernel_launch(void* const* d_in, const int* in_sizes, int n_in,
                              void* d_out, int out_size)
{
    const int*   seq_id      = (const int*)  d_in[0];
    const float* sequences   = (const float*)d_in[1];
    const float* spontaneous = (const float*)d_in[2];
    const float* theta       = (const float*)d_in[3];
    const float* w           = (const float*)d_in[4];
    const float* alpha       = (const float*)d_in[5];
    float* out = (float*)d_out;

    hawkes_kernel<<<1, 1024>>>(seq_id, sequences, spontaneous, theta, w, alpha, out);
}